// round 12
// baseline (speedup 1.0000x reference)
#include <cuda_runtime.h>

// prediction: [32,4,512,512] f32 ; intervals: [32,4,64,2,2] i32 (x2 tensors)
// loss = 14.0 + sum w(comp,c,n)*(birth-death)^2
//   g = GOOD_comp[c]; w = -0.0625/g if n<g else +0.0625/(64-g)
// GOOD_0={1,2,1,3} -> nibbles 0x3121 ; GOOD_1={1,0,2,1} -> 0x1201
// Proven-best structure (R6): 128 blocks x 128 threads, one smem block-reduce,
// release-RED accumulate + acq_rel wrapping arrival counter (replay-safe),
// last arriver acquire-loads the total (14.0 pre-folded) and resets.

#define NBC 128

__device__ float    g_accum = 14.0f;  // reset to 14.0f by last block each run
__device__ unsigned g_count = 0;      // atom.inc wraps at 128 -> replay-safe

__global__ void __launch_bounds__(128, 1)
bd_final_kernel(const float* __restrict__ pred,
                const int*   __restrict__ iv0,
                const int*   __restrict__ iv1,
                float*       __restrict__ out)
{
    const int bc   = blockIdx.x;      // b*4 + c
    const int c    = bc & 3;
    const int tid  = threadIdx.x;     // 0..127
    const int comp = tid >> 6;
    const int n    = tid & 63;

    const int* iv = comp ? iv1 : iv0;
    const int4 co = reinterpret_cast<const int4*>(iv)[bc * 64 + n];

    const float* p = pred + (size_t)bc * (512 * 512);
    const float birth = __ldg(p + ((co.x << 9) | co.y));
    const float death = __ldg(p + ((co.z << 9) | co.w));
    const float d = birth - death;

    const unsigned packed = comp ? 0x1201u : 0x3121u;
    const int g = (packed >> (c * 4)) & 0xF;
    const float w = (n < g) ? (-0.0625f / (float)g)
                            : ( 0.0625f / (float)(64 - g));
    float v = w * d * d;

    // Warp reduce, then 4 warp partials through smem (one BAR).
    #pragma unroll
    for (int off = 16; off > 0; off >>= 1)
        v += __shfl_down_sync(0xFFFFFFFFu, v, off);

    __shared__ float s[4];
    if ((tid & 31) == 0) s[tid >> 5] = v;
    __syncthreads();

    if (tid == 0) {
        const float partial = s[0] + s[1] + s[2] + s[3];
        // Publish partial without a MEMBAR.
        asm volatile("red.release.gpu.global.add.f32 [%0], %1;"
                     :: "l"(&g_accum), "f"(partial) : "memory");
        // Acq-rel arrival counter; the RMW chain orders all release-adds
        // before the last arriver's acquire-load. Wraps to 0 after 128.
        unsigned old;
        asm volatile("atom.acq_rel.gpu.global.inc.u32 %0, [%1], %2;"
                     : "=r"(old) : "l"(&g_count), "r"(NBC - 1u) : "memory");
        if (old == NBC - 1u) {
            float total;
            asm volatile("ld.acquire.gpu.global.f32 %0, [%1];"
                         : "=f"(total) : "l"(&g_accum) : "memory");
            out[0] = total;                                  // 14.0 folded in
            asm volatile("st.global.f32 [%0], 0f41600000;"   // reset to 14.0f
                         :: "l"(&g_accum) : "memory");
        }
    }
}

extern "C" void kernel_launch(void* const* d_in, const int* in_sizes, int n_in,
                              void* d_out, int out_size)
{
    const float* pred = (const float*)d_in[0];
    const int*   iv0  = (const int*)d_in[1];
    const int*   iv1  = (const int*)d_in[2];
    bd_final_kernel<<<NBC, 128>>>(pred, iv0, iv1, (float*)d_out);
}

// round 14
// speedup vs baseline: 1.2917x; 1.2917x over previous
#include <cuda_runtime.h>

// prediction: [32,4,512,512] f32 ; intervals: [32,4,64,2,2] i32 (x2 tensors)
// loss = 14.0 + sum w(comp,c,n)*(birth-death)^2
//   g = GOOD_comp[c]; w = -0.0625/g if n<g else +0.0625/(64-g)
// GOOD_0={1,2,1,3} -> nibbles 0x3121 ; GOOD_1={1,0,2,1} -> 0x1201
//
// Handoff: ONE u64 atomic per block. Each block adds
//   contrib = llrint(partial * 2^24) + 2^40
// so bits >=40 count arrivals while low bits hold the exact fixed-point sum
// (|partial| << 2^14 so per-arrival noise << 2^39; round(old/2^40) = arrivals).
// The add's return value gives the last arriver the complete total directly:
// no release/acquire pair, no second read. Integer adds -> bitwise
// deterministic. Accumulator reset to 0 by the last arriver (replay-safe).

#define NBC 128

__device__ unsigned long long g_acc64 = 0ULL;

__global__ void __launch_bounds__(128, 1)
bd_fix_kernel(const float* __restrict__ pred,
              const int*   __restrict__ iv0,
              const int*   __restrict__ iv1,
              float*       __restrict__ out)
{
    const int bc   = blockIdx.x;      // b*4 + c
    const int c    = bc & 3;
    const int tid  = threadIdx.x;     // 0..127
    const int comp = tid >> 6;
    const int n    = tid & 63;

    const int* iv = comp ? iv1 : iv0;
    const int4 co = reinterpret_cast<const int4*>(iv)[bc * 64 + n];

    const float* p = pred + (size_t)bc * (512 * 512);
    const float birth = __ldg(p + ((co.x << 9) | co.y));
    const float death = __ldg(p + ((co.z << 9) | co.w));
    const float d = birth - death;

    const unsigned packed = comp ? 0x1201u : 0x3121u;
    const int g = (packed >> (c * 4)) & 0xF;
    const float w = (n < g) ? (-0.0625f / (float)g)
                            : ( 0.0625f / (float)(64 - g));
    float v = w * d * d;

    // Warp reduce, then 4 warp partials through smem (one BAR).
    #pragma unroll
    for (int off = 16; off > 0; off >>= 1)
        v += __shfl_down_sync(0xFFFFFFFFu, v, off);

    __shared__ float s[4];
    if ((tid & 31) == 0) s[tid >> 5] = v;
    __syncthreads();

    if (tid == 0) {
        const float partial = s[0] + s[1] + s[2] + s[3];
        const long long fixed = __float2ll_rn(partial * 16777216.0f); // 2^24
        const unsigned long long contrib =
            (unsigned long long)(fixed + (1LL << 40));

        unsigned long long old;
        asm volatile("atom.relaxed.gpu.global.add.u64 %0, [%1], %2;"
                     : "=l"(old) : "l"(&g_acc64), "l"(contrib) : "memory");

        // Arrivals before mine, rounded (|sum noise| << 2^39).
        const unsigned k_prior = (unsigned)((old + (1ULL << 39)) >> 40);
        if (k_prior == NBC - 1) {
            const long long total_fixed =
                (long long)(old + contrib) - ((long long)NBC << 40);
            out[0] = 14.0f + (float)total_fixed * (1.0f / 16777216.0f);
            // Reset for next replay; off the critical path, visible at the
            // next launch boundary.
            const unsigned long long zero = 0ULL;
            asm volatile("st.relaxed.gpu.global.u64 [%0], %1;"
                         :: "l"(&g_acc64), "l"(zero) : "memory");
        }
    }
}

extern "C" void kernel_launch(void* const* d_in, const int* in_sizes, int n_in,
                              void* d_out, int out_size)
{
    const float* pred = (const float*)d_in[0];
    const int*   iv0  = (const int*)d_in[1];
    const int*   iv1  = (const int*)d_in[2];
    bd_fix_kernel<<<NBC, 128>>>(pred, iv0, iv1, (float*)d_out);
}

// round 17
// speedup vs baseline: 1.3413x; 1.0385x over previous
#include <cuda_runtime.h>

// prediction: [32,4,512,512] f32 ; intervals: [32,4,64,2,2] i32 (x2 tensors)
// loss = 14.0 + sum w(comp,c,n)*(birth-death)^2
//   g = GOOD_comp[c]; w = -0.0625/g if n<g else +0.0625/(64-g)
// GOOD_0={1,2,1,3} -> nibbles 0x3121 ; GOOD_1={1,0,2,1} -> 0x1201
//
// Reduction is integer fixed-point end-to-end:
//   per-thread: fi = rint(v * 2^22)  (|v| ~ <=10 -> warp sums fit s32)
//   warp:       REDUX.ADD.S32 (one HW op; float redux doesn't exist on sm_103)
//   block:      4 warp sums via smem, combined in s64
//   grid:       ONE u64 atomic: contrib = block_fixed + 2^40
// bits >=40 count arrivals (|data sum| < 2^39), low bits hold the exact sum.
// Atomic's return value hands the last arriver the total directly; reset
// store is off the critical path (visible next launch boundary).

#define NBC 128

__device__ unsigned long long g_acc64 = 0ULL;

__global__ void __launch_bounds__(128, 1)
bd_fix3_kernel(const float* __restrict__ pred,
               const int*   __restrict__ iv0,
               const int*   __restrict__ iv1,
               float*       __restrict__ out)
{
    const int bc   = blockIdx.x;      // b*4 + c
    const int c    = bc & 3;
    const int tid  = threadIdx.x;     // 0..127
    const int comp = tid >> 6;
    const int n    = tid & 63;

    const int* iv = comp ? iv1 : iv0;
    const int4 co = reinterpret_cast<const int4*>(iv)[bc * 64 + n];

    const float* p = pred + (size_t)bc * (512 * 512);
    const float birth = __ldg(p + ((co.x << 9) | co.y));
    const float death = __ldg(p + ((co.z << 9) | co.w));
    const float d = birth - death;

    const unsigned packed = comp ? 0x1201u : 0x3121u;
    const int g = (packed >> (c * 4)) & 0xF;
    const float w = (n < g) ? (-0.0625f / (float)g)
                            : ( 0.0625f / (float)(64 - g));
    const float v = w * d * d;

    // Per-thread fixed-point (parallel, off the reduce critical path).
    const int fi = __float2int_rn(v * 4194304.0f);        // * 2^22

    // Single HW integer warp reduction (sm_80+): replaces 5-SHFL chain.
    const int wsum = __reduce_add_sync(0xFFFFFFFFu, fi);

    __shared__ int s[4];
    if ((tid & 31) == 0) s[tid >> 5] = wsum;
    __syncthreads();

    if (tid == 0) {
        const long long block_fixed =
            (long long)s[0] + s[1] + s[2] + s[3];
        const unsigned long long contrib =
            (unsigned long long)(block_fixed + (1LL << 40));

        unsigned long long old;
        asm volatile("atom.relaxed.gpu.global.add.u64 %0, [%1], %2;"
                     : "=l"(old) : "l"(&g_acc64), "l"(contrib) : "memory");

        // Arrivals before mine (|data sum| < 2^39 -> exact decode).
        const unsigned k_prior = (unsigned)((old + (1ULL << 39)) >> 40);
        if (k_prior == NBC - 1) {
            const long long total_fixed =
                (long long)(old + contrib) - ((long long)NBC << 40);
            out[0] = 14.0f + (float)total_fixed * (1.0f / 4194304.0f);
            // Reset for next replay; off the critical path.
            const unsigned long long zero = 0ULL;
            asm volatile("st.relaxed.gpu.global.u64 [%0], %1;"
                         :: "l"(&g_acc64), "l"(zero) : "memory");
        }
    }
}

extern "C" void kernel_launch(void* const* d_in, const int* in_sizes, int n_in,
                              void* d_out, int out_size)
{
    const float* pred = (const float*)d_in[0];
    const int*   iv0  = (const int*)d_in[1];
    const int*   iv1  = (const int*)d_in[2];
    bd_fix3_kernel<<<NBC, 128>>>(pred, iv0, iv1, (float*)d_out);
}